// round 8
// baseline (speedup 1.0000x reference)
#include <cuda_runtime.h>
#include <cuda_bf16.h>
#include <cstdint>

// Hybrid embedding gather: out[s,:] = weights[x[s],:]
// x: [8192] int32, weights: [49408, 768] fp32, out: [8192, 768] fp32
//
// Experiment: LDG path and TMA/bulk path each cap at ~2.4 TB/s alone.
// If the caps are per-path (SM-side), driving BOTH simultaneously doubles
// throughput. Blocks 0-511: LDG gather (rows 0-4095, U=8, 16B/thread).
// Blocks 512-1023: bulk-DMA driver (rows 4096-8191, 8 rows in flight).

#define SEQ       8192
#define DIM       768
#define VEC       (DIM / 4)     // 192 float4 per row
#define ROW_BYTES 3072
#define U         8             // rows per CTA (both halves)
#define HALF_CTAS 512           // 512 CTAs per path
#define BLK       192

__device__ __forceinline__ uint32_t smem_u32(const void* p) {
    uint32_t a;
    asm("{ .reg .u64 t; cvta.to.shared.u64 t, %1; cvt.u32.u64 %0, t; }"
        : "=r"(a) : "l"(p));
    return a;
}

__global__ void __launch_bounds__(BLK) embed_hybrid_kernel(
    const int* __restrict__ x,
    const float4* __restrict__ weights,   // [VOCAB, VEC]
    float4* __restrict__ out)             // [SEQ, VEC]
{
    __shared__ __align__(128) char buf[U][ROW_BYTES];
    __shared__ __align__(8)  unsigned long long mbar[U];

    const int b = blockIdx.x;

    if (b < HALF_CTAS) {
        // ---------- LDG half: rows [0, 4096) ----------
        const int t  = threadIdx.x;
        const int s0 = b * U;

        int rows[U];
#pragma unroll
        for (int u = 0; u < U; u++)
            rows[u] = __ldg(&x[s0 + u]);

        float4 v[U];
#pragma unroll
        for (int u = 0; u < U; u++)
            v[u] = weights[(size_t)rows[u] * VEC + t];

#pragma unroll
        for (int u = 0; u < U; u++)
            out[(size_t)(s0 + u) * VEC + t] = v[u];
        return;
    }

    // ---------- Bulk-DMA half: rows [4096, 8192) ----------
    if (threadIdx.x != 0) return;   // single driver thread

    const int s0 = HALF_CTAS * U + (b - HALF_CTAS) * U;
    const uint32_t mbar0 = smem_u32(&mbar[0]);
    const uint32_t buf0  = smem_u32(&buf[0][0]);
    const char* wbytes = (const char*)weights;
    char*       obytes = (char*)out;

#pragma unroll
    for (int i = 0; i < U; i++)
        asm volatile("mbarrier.init.shared.b64 [%0], 1;" :: "r"(mbar0 + i * 8) : "memory");
    asm volatile("fence.proxy.async.shared::cta;" ::: "memory");

    // Queue all row loads (8 x 3072 B in flight)
#pragma unroll
    for (int i = 0; i < U; i++) {
        const int row = __ldg(&x[s0 + i]);
        const uint32_t mb = mbar0 + i * 8;
        asm volatile("mbarrier.arrive.expect_tx.shared.b64 _, [%0], %1;"
                     :: "r"(mb), "r"((uint32_t)ROW_BYTES) : "memory");
        asm volatile(
            "cp.async.bulk.shared::cta.global.mbarrier::complete_tx::bytes "
            "[%0], [%1], %2, [%3];"
            :: "r"(buf0 + i * ROW_BYTES),
               "l"(wbytes + (size_t)row * ROW_BYTES),
               "r"((uint32_t)ROW_BYTES),
               "r"(mb)
            : "memory");
    }

    // Drain: wait each load, then bulk-store the row out
#pragma unroll
    for (int i = 0; i < U; i++) {
        const uint32_t mb = mbar0 + i * 8;
        asm volatile(
            "{\n\t"
            ".reg .pred P1;\n\t"
            "WL_%=:\n\t"
            "mbarrier.try_wait.parity.acquire.cta.shared::cta.b64 P1, [%0], 0, 0x989680;\n\t"
            "@P1 bra.uni WD_%=;\n\t"
            "bra.uni WL_%=;\n\t"
            "WD_%=:\n\t"
            "}" :: "r"(mb) : "memory");
        asm volatile("fence.proxy.async.shared::cta;" ::: "memory");
        asm volatile(
            "cp.async.bulk.global.shared::cta.bulk_group [%0], [%1], %2;"
            :: "l"(obytes + (size_t)(s0 + i) * ROW_BYTES),
               "r"(buf0 + i * ROW_BYTES),
               "r"((uint32_t)ROW_BYTES)
            : "memory");
        asm volatile("cp.async.bulk.commit_group;" ::: "memory");
    }

    asm volatile("cp.async.bulk.wait_group 0;" ::: "memory");
}

extern "C" void kernel_launch(void* const* d_in, const int* in_sizes, int n_in,
                              void* d_out, int out_size) {
    const int*    x = (const int*)d_in[0];
    const float4* w = (const float4*)d_in[1];
    float4*       o = (float4*)d_out;
    embed_hybrid_kernel<<<SEQ / U, BLK>>>(x, w, o);
}